// round 16
// baseline (speedup 1.0000x reference)
#include <cuda_runtime.h>
#include <math.h>

typedef unsigned long long u64;
typedef ulonglong2 u64x2;

#define Hn   256
#define Wn   256
#define CIN  64
#define COUT 64
#define Bn   16

__device__ __forceinline__ u64 f2u(float lo, float hi) {
    u64 r; asm("mov.b64 %0, {%1,%2};" : "=l"(r) : "f"(lo), "f"(hi)); return r;
}
__device__ __forceinline__ float2 u2f(u64 v) {
    float2 r; asm("mov.b64 {%0,%1}, %2;" : "=f"(r.x), "=f"(r.y) : "l"(v)); return r;
}
__device__ __forceinline__ u64 ffma2(u64 a, u64 b, u64 c) {
    u64 d; asm("fma.rn.f32x2 %0, %1, %2, %3;" : "=l"(d) : "l"(a), "l"(b), "l"(c));
    return d;
}
__device__ __forceinline__ u64 fadd2(u64 a, u64 b) {
    u64 d; asm("add.rn.f32x2 %0, %1, %2;" : "=l"(d) : "l"(a), "l"(b));
    return d;
}
__device__ __forceinline__ u64 fsub2(u64 a, u64 b) {
    return fadd2(a, b ^ 0x8000000080000000ull);
}
__device__ __forceinline__ unsigned smem_u32(const void* p) {
    unsigned a;
    asm("{ .reg .u64 t; cvta.to.shared.u64 t, %1; cvt.u32.u64 %0, t; }"
        : "=r"(a) : "l"(p));
    return a;
}

// g_X is MODE-MAJOR: [mode][b*CIN + i].  g_S stays b-major: [bo][mode].
__device__ u64 g_X[1024 * Bn * CIN];
__device__ u64 g_S[Bn * COUT * 1024];
// Transposed weights: [mode][io]
__device__ float g_Wt[1024 * 4096];

// Precomputed twiddle tables
__device__ __align__(16) float2 g_tab_cs[65 * 32];    // fwd stage1: (c, -s) [w*32+kx]
__device__ __align__(16) float4 g_tab_t4[256];        // fwd stage2: (c, c, s, s)
__device__ __align__(16) float2 g_tab_ci[32 * 68];    // inv C2: (c, s) [kk*68+w] padded
__device__ __align__(16) float4 g_tab_t4i[256];       // inv C1: (c, s, -s, c)

// ---------------------------------------------------------------------------
__global__ __launch_bounds__(256) void init_tables() {
    const int t = blockIdx.x * 256 + threadIdx.x;
    if (t < 65 * 32) {
        int w = t >> 5, kx = t & 31;
        float sv, cv;
        sincospif(((w * kx) & 255) * (2.0f / 256.0f), &sv, &cv);
        g_tab_cs[t] = make_float2(cv, -sv);
    }
    if (t < 32 * 65) {
        int kk = t / 65, w = t - kk * 65;
        float sv, cv;
        sincospif(((kk * w) & 255) * (2.0f / 256.0f), &sv, &cv);
        g_tab_ci[kk * 68 + w] = make_float2(cv, sv);
    }
    if (t < 256) {
        float sv, cv;
        sincospif(t * (2.0f / 256.0f), &sv, &cv);
        g_tab_t4[t]  = make_float4(cv, cv, sv, sv);
        g_tab_t4i[t] = make_float4(cv, sv, -sv, cv);
    }
}

// ---------------------------------------------------------------------------
// Forward v7: stage1 retiled (4kx x 2row threads, tap-split halves, partial-D
// reduction).  Fold / stage2 / pipeline unchanged.
// smem: cs[65][32] f2 | t4[256] f4 | raw[32][256] f32 | xq[32][65] u64x2 |
//       x64[32] u64 | D[32][32] u64 | Dh[32][32] u64   total 103424 B
// ---------------------------------------------------------------------------
#define FWD_SMEM_BYTES (65*32*8 + 256*16 + 32*256*4 + 32*65*16 + 32*8 + 2*32*32*8)

__global__ __launch_bounds__(256, 2) void fwd_kernel(const float* __restrict__ x,
                                                     const float* __restrict__ wts) {
    extern __shared__ char smraw[];
    float2* s_cs  = (float2*)smraw;
    float4* s_t4  = (float4*)(s_cs + 65 * 32);
    float*  s_raw = (float*)(s_t4 + 256);
    u64x2*  s_xq  = (u64x2*)(s_raw + 32 * 256);
    u64*    s_x64 = (u64*)(s_xq + 32 * 65);
    u64*    s_D   = s_x64 + 32;
    u64*    s_Dh  = s_D + 32 * 32;

    const int t  = threadIdx.x;
    const int bi = blockIdx.x;
    const float* xp = x + (size_t)bi * (Hn * Wn);

    const unsigned raw_base = smem_u32(s_raw);
    {
        #pragma unroll
        for (int j = 0; j < 8; ++j) {
            int e = t + j * 256;
            const float* src = xp + e * 4;
            unsigned dst = raw_base + e * 16;
            asm volatile("cp.async.ca.shared.global [%0], [%1], 16;"
                         :: "r"(dst), "l"(src));
        }
        asm volatile("cp.async.commit_group;");
    }

    // ---- load twiddle tables (L2-broadcast)
    #pragma unroll
    for (int e = t; e < 1040; e += 256)
        ((float4*)s_cs)[e] = ((const float4*)g_tab_cs)[e];
    s_t4[t] = g_tab_t4[t];

    // ---- weight transpose: 4 tiles per block, s_D as scratch
    {
        float* tile = (float*)s_D;
        const int tx = t & 31, ty = t >> 5;
        #pragma unroll
        for (int k = 0; k < 4; ++k) {
            int tid = bi * 4 + k;
            int io0 = (tid & 127) * 32;
            int m0  = (tid >> 7) * 32;
            #pragma unroll
            for (int j = ty; j < 32; j += 8)
                tile[j * 33 + tx] = wts[(size_t)(io0 + j) * 1024 + m0 + tx];
            __syncthreads();
            #pragma unroll
            for (int j = ty; j < 32; j += 8)
                g_Wt[(size_t)(m0 + j) * 4096 + io0 + tx] = tile[tx * 33 + j];
            __syncthreads();
        }
    }

    const int warp = t >> 5, lane = t & 31;
    // stage2 mapping (unchanged)
    const int kxg  = warp & 1;
    const int rg   = warp >> 1;
    const int kl   = lane & 7;
    const int rl   = lane >> 3;
    const int kx0  = kxg * 16 + kl * 2;
    const int row0 = rg * 8 + rl * 2;
    // stage1 mapping (tap-split): 4 warps cover 32kx x 32rows; half = taps
    const int s1_half = warp >> 2;               // 0: taps 0..31, 1: taps 32..64
    const int s1_kxh  = warp & 1;
    const int s1_rwh  = (warp >> 1) & 1;
    const int s1_klq  = lane & 3;
    const int s1_rlq  = lane >> 2;
    const int s1_kx0  = s1_kxh * 16 + s1_klq * 4;     // even
    const int s1_row0 = s1_rwh * 16 + s1_rlq * 2;

    u64 X[2][2];
    X[0][0] = X[0][1] = X[1][0] = X[1][1] = 0ull;

    const u64* cs64 = (const u64*)s_cs;

    asm volatile("cp.async.wait_group 0;");
    __syncthreads();

    for (int c = 0; c < 8; ++c) {
        // ---- fold raw (smem) -> xq / x64
        #pragma unroll 2
        for (int idx = t; idx < 32 * 64; idx += 256) {
            int r = idx >> 6;
            int w = idx & 63;
            const float* row = s_raw + r * 256;
            u64x2 v;
            if (w == 0) {
                float x0 = row[0], x128 = row[128];
                v.x = f2u(x0 + x128, 0.f);
                v.y = f2u(x0 - x128, 0.f);
            } else {
                float xa = row[w],       xb = row[256 - w];
                float xc = row[128 - w], xd = row[128 + w];
                v.x = f2u(xa + xb + xc + xd, xa - xb - xc + xd);
                v.y = f2u(xa + xb - xc - xd, xa - xb + xc - xd);
            }
            s_xq[r * 65 + w] = v;
        }
        if (t < 32) {
            const float* row = s_raw + t * 256;
            float a = row[64], b = row[192];
            s_x64[t] = f2u(a + b, a - b);
        }
        __syncthreads();

        if (c < 7) {
            const float* xc = xp + (size_t)(c + 1) * 32 * Wn;
            #pragma unroll
            for (int j = 0; j < 8; ++j) {
                int e = t + j * 256;
                const float* src = xc + e * 4;
                unsigned dst = raw_base + e * 16;
                asm volatile("cp.async.ca.shared.global [%0], [%1], 16;"
                             :: "r"(dst), "l"(src));
            }
            asm volatile("cp.async.commit_group;");
        }

        // ---- stage 1 (retiled): each half-block does half the taps
        {
            u64 a0[4] = {0ull, 0ull, 0ull, 0ull};   // row s1_row0
            u64 a1[4] = {0ull, 0ull, 0ull, 0ull};   // row s1_row0+1
            const int wlo = s1_half ? 32 : 0;
            const int whi = s1_half ? 64 : 32;
            #pragma unroll 4
            for (int w = wlo; w < whi; ++w) {
                u64x2 tw0 = *(const u64x2*)&cs64[w * 32 + s1_kx0];
                u64x2 tw1 = *(const u64x2*)&cs64[w * 32 + s1_kx0 + 2];
                u64x2 v0  = s_xq[s1_row0 * 65 + w];
                u64x2 v1  = s_xq[(s1_row0 + 1) * 65 + w];
                a0[0] = ffma2(v0.x, tw0.x, a0[0]);
                a0[1] = ffma2(v0.y, tw0.y, a0[1]);
                a0[2] = ffma2(v0.x, tw1.x, a0[2]);
                a0[3] = ffma2(v0.y, tw1.y, a0[3]);
                a1[0] = ffma2(v1.x, tw0.x, a1[0]);
                a1[1] = ffma2(v1.y, tw0.y, a1[1]);
                a1[2] = ffma2(v1.x, tw1.x, a1[2]);
                a1[3] = ffma2(v1.y, tw1.y, a1[3]);
            }
            if (s1_half) {   // tap w = 64: raw (xe64, xo64) for both parities
                u64x2 tw0 = *(const u64x2*)&cs64[64 * 32 + s1_kx0];
                u64x2 tw1 = *(const u64x2*)&cs64[64 * 32 + s1_kx0 + 2];
                u64 v0 = s_x64[s1_row0];
                u64 v1 = s_x64[s1_row0 + 1];
                a0[0] = ffma2(v0, tw0.x, a0[0]);
                a0[1] = ffma2(v0, tw0.y, a0[1]);
                a0[2] = ffma2(v0, tw1.x, a0[2]);
                a0[3] = ffma2(v0, tw1.y, a0[3]);
                a1[0] = ffma2(v1, tw0.x, a1[0]);
                a1[1] = ffma2(v1, tw0.y, a1[1]);
                a1[2] = ffma2(v1, tw1.x, a1[2]);
                a1[3] = ffma2(v1, tw1.y, a1[3]);
            }
            u64* dst = s1_half ? s_Dh : s_D;
            u64x2 p;
            p.x = a0[0]; p.y = a0[1];
            *(u64x2*)&dst[s1_row0 * 32 + s1_kx0] = p;
            p.x = a0[2]; p.y = a0[3];
            *(u64x2*)&dst[s1_row0 * 32 + s1_kx0 + 2] = p;
            p.x = a1[0]; p.y = a1[1];
            *(u64x2*)&dst[(s1_row0 + 1) * 32 + s1_kx0] = p;
            p.x = a1[2]; p.y = a1[3];
            *(u64x2*)&dst[(s1_row0 + 1) * 32 + s1_kx0 + 2] = p;
        }
        __syncthreads();

        // ---- reduce the two tap-halves: D += Dh
        #pragma unroll
        for (int e2 = t; e2 < 512; e2 += 256) {
            u64x2 pA = ((u64x2*)s_D)[e2];
            u64x2 pB = ((u64x2*)s_Dh)[e2];
            pA.x = fadd2(pA.x, pB.x);
            pA.y = fadd2(pA.y, pB.y);
            ((u64x2*)s_D)[e2] = pA;
        }
        __syncthreads();

        // ---- stage 2 (unchanged)
        const int h0 = c * 32;
        #pragma unroll 4
        for (int r = 0; r < 32; ++r) {
            const int h = h0 + r;
            u64x2 dp = *(const u64x2*)&s_D[r * 32 + kx0];
            float2 d0 = u2f(dp.x), d1 = u2f(dp.y);
            u64 dq0 = f2u(d0.y, -d0.x);
            u64 dq1 = f2u(d1.y, -d1.x);
            u64x2 e0 = *(const u64x2*)&s_t4[(row0 * h) & 255];
            u64x2 e1 = *(const u64x2*)&s_t4[((row0 + 1) * h) & 255];
            X[0][0] = ffma2(dp.x, e0.x, X[0][0]);
            X[0][0] = ffma2(dq0,  e0.y, X[0][0]);
            X[0][1] = ffma2(dp.y, e0.x, X[0][1]);
            X[0][1] = ffma2(dq1,  e0.y, X[0][1]);
            X[1][0] = ffma2(dp.x, e1.x, X[1][0]);
            X[1][0] = ffma2(dq0,  e1.y, X[1][0]);
            X[1][1] = ffma2(dp.y, e1.x, X[1][1]);
            X[1][1] = ffma2(dq1,  e1.y, X[1][1]);
        }
        if (c < 7) asm volatile("cp.async.wait_group 0;");
        __syncthreads();
    }

    // mode-major store: g_X[m][bi]
    #pragma unroll
    for (int j = 0; j < 2; ++j)
        #pragma unroll
        for (int i = 0; i < 2; ++i)
            g_X[(size_t)((row0 + j) * 32 + kx0 + i) * 1024 + bi] = X[j][i];
}

// ---------------------------------------------------------------------------
// Mix (unchanged): fully coalesced loads
// ---------------------------------------------------------------------------
__global__ __launch_bounds__(256) void mix_kernel() {
    __shared__ float s_W[CIN * COUT];
    __shared__ u64   s_X[Bn * CIN];
    const int t = threadIdx.x;
    const int m = blockIdx.x;

    {
        const float4* wp4 = (const float4*)(g_Wt + (size_t)m * 4096);
        #pragma unroll
        for (int e = t; e < 1024; e += 256)
            ((float4*)s_W)[e] = wp4[e];
        const u64x2* xp2 = (const u64x2*)(g_X + (size_t)m * 1024);
        #pragma unroll
        for (int e = t; e < 512; e += 256)
            ((u64x2*)s_X)[e] = xp2[e];
    }
    __syncthreads();

    const int o  = t & 63;
    const int bq = t >> 6;
    u64 acc[4] = {0ull, 0ull, 0ull, 0ull};

    #pragma unroll 8
    for (int i = 0; i < CIN; ++i) {
        float wv = s_W[i * 64 + o];
        u64 wp = f2u(wv, wv);
        #pragma unroll
        for (int j = 0; j < 4; ++j)
            acc[j] = ffma2(s_X[(bq * 4 + j) * 64 + i], wp, acc[j]);
    }
    #pragma unroll
    for (int j = 0; j < 4; ++j)
        g_S[((size_t)(bq * 4 + j) * 64 + o) * 1024 + m] = acc[j];
}

// ---------------------------------------------------------------------------
// Inverse v5 (unchanged hot loops): tables loaded from global.
// ---------------------------------------------------------------------------
#define INV_SMEM_BYTES (32*68*8 + 256*16 + 1024*8 + 2*32*34*8)

__global__ __launch_bounds__(256) void inv_kernel(const float* __restrict__ bias,
                                                  float* __restrict__ out) {
    extern __shared__ char smraw[];
    float2* s_ci  = (float2*)smraw;                 // [kk*68 + w], w in [0,64]
    float4* s_t4i = (float4*)(s_ci + 32 * 68);      // [n] = (c, s, -s, c)
    u64*    s_S   = (u64*)(s_t4i + 256);            // [ky*32 + kx], pre-scaled
    u64*    s_Ga  = s_S + 1024;                     // [kk*34 + r], r in 0..31
    u64*    s_Gb  = s_Ga + 32 * 34;                 // +128 twin rows

    const int t  = threadIdx.x;
    const int bo = blockIdx.x;
    const int o  = bo & 63;

    #pragma unroll
    for (int e = t; e < 1088; e += 256)
        ((float4*)s_ci)[e] = ((const float4*)g_tab_ci)[e];
    s_t4i[t] = g_tab_t4i[t];

    for (int e = t; e < 1024; e += 256) {
        float2 v  = u2f(g_S[(size_t)bo * 1024 + e]);
        float sc  = ((e & 31) == 0 ? 1.f : 2.f) * (1.f / 65536.f);
        s_S[e] = f2u(v.x * sc, v.y * sc);
    }
    const float bias_o = bias[o];
    __syncthreads();

    const int kx = t & 31, r2 = t >> 5;
    const int wp   = t & 31;
    const int w0   = wp * 2;
    const int rg   = (t >> 5) & 3;
    const int half = t >> 7;
    const int r0   = rg * 8;

    float* yp = out + (size_t)bo * (Hn * Wn);
    const u64* Gh = half ? s_Gb : s_Ga;

    for (int cp = 0; cp < 4; ++cp) {
        const int hb32 = cp * 32;

        #pragma unroll
        for (int sub = 0; sub < 2; ++sub) {
            const int h1 = hb32 + 16 * sub + 2 * r2;
            const int h2 = h1 + 1;
            u64 aE1 = 0ull, aO1 = 0ull, aE2 = 0ull, aO2 = 0ull;
            #pragma unroll 4
            for (int ky = 0; ky < 32; ky += 2) {
                float2 sv = u2f(s_S[ky * 32 + kx]);
                u64 sxx = f2u(sv.x, sv.x);
                u64 syy = f2u(sv.y, sv.y);
                u64x2 e1 = *(const u64x2*)&s_t4i[(ky * h1) & 255];
                u64x2 e2 = *(const u64x2*)&s_t4i[(ky * h2) & 255];
                aE1 = ffma2(sxx, e1.x, aE1);
                aE1 = ffma2(syy, e1.y, aE1);
                aE2 = ffma2(sxx, e2.x, aE2);
                aE2 = ffma2(syy, e2.y, aE2);
                float2 sw = u2f(s_S[(ky + 1) * 32 + kx]);
                u64 txx = f2u(sw.x, sw.x);
                u64 tyy = f2u(sw.y, sw.y);
                u64x2 f1  = *(const u64x2*)&s_t4i[((ky + 1) * h1) & 255];
                u64x2 f2v = *(const u64x2*)&s_t4i[((ky + 1) * h2) & 255];
                aO1 = ffma2(txx, f1.x, aO1);
                aO1 = ffma2(tyy, f1.y, aO1);
                aO2 = ffma2(txx, f2v.x, aO2);
                aO2 = ffma2(tyy, f2v.y, aO2);
            }
            u64x2 ga; ga.x = fadd2(aE1, aO1); ga.y = fadd2(aE2, aO2);
            u64x2 gb; gb.x = fsub2(aE1, aO1); gb.y = fsub2(aE2, aO2);
            *(u64x2*)&s_Ga[kx * 34 + 16 * sub + 2 * r2] = ga;
            *(u64x2*)&s_Gb[kx * 34 + 16 * sub + 2 * r2] = gb;
        }
        __syncthreads();

        {
            u64 aE[2][8], aO[2][8];
            #pragma unroll
            for (int wv = 0; wv < 2; ++wv)
                #pragma unroll
                for (int r = 0; r < 8; ++r) { aE[wv][r] = 0ull; aO[wv][r] = 0ull; }

            #pragma unroll 2
            for (int kk = 0; kk < 32; kk += 2) {
                u64x2 twE = *(const u64x2*)&s_ci[kk * 68 + w0];
                u64x2 twO = *(const u64x2*)&s_ci[(kk + 1) * 68 + w0];
                const u64* GE = &Gh[kk * 34 + r0];
                const u64* GO = &Gh[(kk + 1) * 34 + r0];
                #pragma unroll
                for (int rr = 0; rr < 4; ++rr) {
                    u64x2 gE = *(const u64x2*)&GE[2 * rr];
                    u64x2 gO = *(const u64x2*)&GO[2 * rr];
                    aE[0][2*rr]   = ffma2(gE.x, twE.x, aE[0][2*rr]);
                    aE[0][2*rr+1] = ffma2(gE.y, twE.x, aE[0][2*rr+1]);
                    aE[1][2*rr]   = ffma2(gE.x, twE.y, aE[1][2*rr]);
                    aE[1][2*rr+1] = ffma2(gE.y, twE.y, aE[1][2*rr+1]);
                    aO[0][2*rr]   = ffma2(gO.x, twO.x, aO[0][2*rr]);
                    aO[0][2*rr+1] = ffma2(gO.y, twO.x, aO[0][2*rr+1]);
                    aO[1][2*rr]   = ffma2(gO.x, twO.y, aO[1][2*rr]);
                    aO[1][2*rr+1] = ffma2(gO.y, twO.y, aO[1][2*rr+1]);
                }
            }

            #pragma unroll
            for (int r = 0; r < 8; ++r) {
                const int h = hb32 + half * 128 + r0 + r;
                float2 pq0 = u2f(fadd2(aE[0][r], aO[0][r]));
                float2 rt0 = u2f(fsub2(aE[0][r], aO[0][r]));
                float2 pq1 = u2f(fadd2(aE[1][r], aO[1][r]));
                float2 rt1 = u2f(fsub2(aE[1][r], aO[1][r]));
                float y0  = pq0.x - pq0.y + bias_o;
                float y1  = pq1.x - pq1.y + bias_o;
                float m0  = pq0.x + pq0.y + bias_o;
                float m1  = pq1.x + pq1.y + bias_o;
                float p0  = rt0.x + rt0.y + bias_o;
                float p1  = rt1.x + rt1.y + bias_o;
                float q0  = rt0.x - rt0.y + bias_o;
                float q1  = rt1.x - rt1.y + bias_o;
                *(float2*)&yp[h * 256 + w0] = make_float2(y0, y1);
                *(float2*)&yp[h * 256 + 128 + w0] = make_float2(q0, q1);
                yp[h * 256 + (128 - w0)] = p0;
                yp[h * 256 + (127 - w0)] = p1;
                yp[h * 256 + (255 - w0)] = m1;
                if (wp) yp[h * 256 + (256 - w0)] = m0;
            }
        }

        if (t < 64) {
            const u64* G = (t >= 32) ? s_Gb : s_Ga;
            const int r = t & 31;
            float A = 0.f, B = 0.f;
            #pragma unroll
            for (int kk = 0; kk < 32; kk += 4) {
                A += u2f(G[kk * 34 + r]).x;
                A -= u2f(G[(kk + 2) * 34 + r]).x;
                B += u2f(G[(kk + 1) * 34 + r]).y;
                B -= u2f(G[(kk + 3) * 34 + r]).y;
            }
            const int h = hb32 + ((t >= 32) ? 128 : 0) + r;
            yp[h * 256 + 64]  = A - B + bias_o;
            yp[h * 256 + 192] = A + B + bias_o;
        }
        __syncthreads();
    }
}

// ---------------------------------------------------------------------------
extern "C" void kernel_launch(void* const* d_in, const int* in_sizes, int n_in,
                              void* d_out, int out_size) {
    const float* x    = (const float*)d_in[0];
    const float* wts  = (const float*)d_in[1];
    const float* bias = (const float*)d_in[2];
    float* out = (float*)d_out;

    cudaFuncSetAttribute(fwd_kernel, cudaFuncAttributeMaxDynamicSharedMemorySize,
                         FWD_SMEM_BYTES);
    cudaFuncSetAttribute(inv_kernel, cudaFuncAttributeMaxDynamicSharedMemorySize,
                         INV_SMEM_BYTES);

    init_tables<<<9, 256>>>();
    fwd_kernel<<<Bn * CIN, 256, FWD_SMEM_BYTES>>>(x, wts);
    mix_kernel<<<1024, 256>>>();
    inv_kernel<<<Bn * COUT, 256, INV_SMEM_BYTES>>>(bias, out);
}

// round 17
// speedup vs baseline: 1.0299x; 1.0299x over previous
#include <cuda_runtime.h>
#include <math.h>

typedef unsigned long long u64;
typedef ulonglong2 u64x2;

#define Hn   256
#define Wn   256
#define CIN  64
#define COUT 64
#define Bn   16

__device__ __forceinline__ u64 f2u(float lo, float hi) {
    u64 r; asm("mov.b64 %0, {%1,%2};" : "=l"(r) : "f"(lo), "f"(hi)); return r;
}
__device__ __forceinline__ float2 u2f(u64 v) {
    float2 r; asm("mov.b64 {%0,%1}, %2;" : "=f"(r.x), "=f"(r.y) : "l"(v)); return r;
}
__device__ __forceinline__ u64 ffma2(u64 a, u64 b, u64 c) {
    u64 d; asm("fma.rn.f32x2 %0, %1, %2, %3;" : "=l"(d) : "l"(a), "l"(b), "l"(c));
    return d;
}
__device__ __forceinline__ u64 fadd2(u64 a, u64 b) {
    u64 d; asm("add.rn.f32x2 %0, %1, %2;" : "=l"(d) : "l"(a), "l"(b));
    return d;
}
__device__ __forceinline__ u64 fsub2(u64 a, u64 b) {
    return fadd2(a, b ^ 0x8000000080000000ull);
}
__device__ __forceinline__ unsigned smem_u32(const void* p) {
    unsigned a;
    asm("{ .reg .u64 t; cvta.to.shared.u64 t, %1; cvt.u32.u64 %0, t; }"
        : "=r"(a) : "l"(p));
    return a;
}

// g_X is MODE-MAJOR: [mode][b*CIN + i].  g_S stays b-major: [bo][mode].
__device__ u64 g_X[1024 * Bn * CIN];
__device__ u64 g_S[Bn * COUT * 1024];
// Transposed weights: [mode][io]
__device__ float g_Wt[1024 * 4096];

// Precomputed twiddle tables
__device__ __align__(16) float2 g_tab_cs[65 * 32];    // fwd stage1: (c, -s) [w*32+kx]
__device__ __align__(16) float4 g_tab_t4[256];        // fwd stage2: (c, c, s, s)
__device__ __align__(16) float2 g_tab_ci[32 * 68];    // inv C2: (c, s) [kk*68+w] padded
__device__ __align__(16) float4 g_tab_t4i[256];       // inv C1: (c, s, -s, c)

// ---------------------------------------------------------------------------
__global__ __launch_bounds__(256) void init_tables() {
    const int t = blockIdx.x * 256 + threadIdx.x;
    if (t < 65 * 32) {
        int w = t >> 5, kx = t & 31;
        float sv, cv;
        sincospif(((w * kx) & 255) * (2.0f / 256.0f), &sv, &cv);
        g_tab_cs[t] = make_float2(cv, -sv);
    }
    if (t < 32 * 65) {
        int kk = t / 65, w = t - kk * 65;
        float sv, cv;
        sincospif(((kk * w) & 255) * (2.0f / 256.0f), &sv, &cv);
        g_tab_ci[kk * 68 + w] = make_float2(cv, sv);
    }
    if (t < 256) {
        float sv, cv;
        sincospif(t * (2.0f / 256.0f), &sv, &cv);
        g_tab_t4[t]  = make_float4(cv, cv, sv, sv);
        g_tab_t4i[t] = make_float4(cv, sv, -sv, cv);
    }
}

// ---------------------------------------------------------------------------
// Forward v9: in-place quarter-fold (raw and xq share one padded buffer) ->
// smem 62464 B -> 3 blocks/SM.  Hot loops identical to the proven R13 code.
// smem: cs[65][32] f2 | t4[256] f4 | xr[32 rows x 1040 B] | x64[32] u64 |
//       D[32][32] u64       total 62464 B
// ---------------------------------------------------------------------------
#define FWD_SMEM_BYTES (65*32*8 + 256*16 + 32*1040 + 32*8 + 32*32*8)

// xq view of the in-place buffer
#define XQ(base, r, w) (*(u64x2*)((char*)(base) + (r) * 1040 + (w) * 16))

__global__ __launch_bounds__(256, 3) void fwd_kernel(const float* __restrict__ x,
                                                     const float* __restrict__ wts) {
    extern __shared__ char smraw[];
    float2* s_cs  = (float2*)smraw;                  // [w*32 + kx]
    float4* s_t4  = (float4*)(s_cs + 65 * 32);       // [n]
    char*   s_xr  = (char*)(s_t4 + 256);             // 32 rows x 1040 B (raw/xq)
    u64*    s_x64 = (u64*)(s_xr + 32 * 1040);        // [r]
    u64*    s_D   = s_x64 + 32;                      // [r*32 + kx]

    const int t  = threadIdx.x;
    const int bi = blockIdx.x;
    const float* xp = x + (size_t)bi * (Hn * Wn);

    const unsigned xr_base = smem_u32(s_xr);
    // issue cp.async for chunk 0 into padded rows
    {
        #pragma unroll
        for (int j = 0; j < 8; ++j) {
            int e = t + j * 256;
            int r = e >> 6, w16 = e & 63;
            const float* src = xp + r * 256 + w16 * 4;
            unsigned dst = xr_base + r * 1040 + w16 * 16;
            asm volatile("cp.async.ca.shared.global [%0], [%1], 16;"
                         :: "r"(dst), "l"(src));
        }
        asm volatile("cp.async.commit_group;");
    }

    // load twiddle tables (L2-broadcast)
    #pragma unroll
    for (int e = t; e < 1040; e += 256)
        ((float4*)s_cs)[e] = ((const float4*)g_tab_cs)[e];
    s_t4[t] = g_tab_t4[t];

    // weight transpose: 4 tiles per block, s_D as scratch (4224 B < 8192)
    {
        float* tile = (float*)s_D;
        const int tx = t & 31, ty = t >> 5;
        #pragma unroll
        for (int k = 0; k < 4; ++k) {
            int tid = bi * 4 + k;
            int io0 = (tid & 127) * 32;
            int m0  = (tid >> 7) * 32;
            #pragma unroll
            for (int j = ty; j < 32; j += 8)
                tile[j * 33 + tx] = wts[(size_t)(io0 + j) * 1024 + m0 + tx];
            __syncthreads();
            #pragma unroll
            for (int j = ty; j < 32; j += 8)
                g_Wt[(size_t)(m0 + j) * 4096 + io0 + tx] = tile[tx * 33 + j];
            __syncthreads();
        }
    }

    const int warp = t >> 5, lane = t & 31;
    const int kxg  = warp & 1;
    const int rg   = warp >> 1;
    const int kl   = lane & 7;
    const int rl   = lane >> 3;
    const int kx0  = kxg * 16 + kl * 2;
    const int row0 = rg * 8 + rl * 2;

    // fold mapping: 16 rows per sub-pass; 16 threads per row, 4 w each
    const int f_r = t >> 4;        // 0..15 (+16 for sub 1)
    const int f_j = t & 15;        // w-set {j, j+16, j+32, j+48}

    u64 X[2][2];
    X[0][0] = X[0][1] = X[1][0] = X[1][1] = 0ull;

    const u64* cs64 = (const u64*)s_cs;

    asm volatile("cp.async.wait_group 0;");
    __syncthreads();

    for (int c = 0; c < 8; ++c) {
        // ---- in-place quarter-fold, two 16-row sub-passes
        #pragma unroll
        for (int sub = 0; sub < 2; ++sub) {
            const int r = sub * 16 + f_r;
            const float* row = (const float*)(s_xr + r * 1040);
            float va[4], vb[4], vc[4], vd[4];
            float e64a = 0.f, e64b = 0.f;
            #pragma unroll
            for (int k = 0; k < 4; ++k) {
                const int w = f_j + k * 16;
                if (w == 0) {            // only f_j==0, k==0
                    va[k] = row[0]; vb[k] = row[128];
                    vc[k] = 0.f;    vd[k] = 0.f;
                } else {
                    va[k] = row[w];       vb[k] = row[256 - w];
                    vc[k] = row[128 - w]; vd[k] = row[128 + w];
                }
            }
            if (f_j == 0) { e64a = row[64]; e64b = row[192]; }
            __syncthreads();     // all reads done before any writes
            #pragma unroll
            for (int k = 0; k < 4; ++k) {
                const int w = f_j + k * 16;
                u64x2 v;
                if (w == 0) {
                    v.x = f2u(va[k] + vb[k], 0.f);
                    v.y = f2u(va[k] - vb[k], 0.f);
                } else {
                    v.x = f2u(va[k] + vb[k] + vc[k] + vd[k],
                              va[k] - vb[k] - vc[k] + vd[k]);
                    v.y = f2u(va[k] + vb[k] - vc[k] - vd[k],
                              va[k] - vb[k] + vc[k] - vd[k]);
                }
                XQ(s_xr, r, w) = v;
            }
            if (f_j == 0) s_x64[r] = f2u(e64a + e64b, e64a - e64b);
            __syncthreads();     // sub complete (also gates next sub / stage1)
        }

        // ---- stage 1: quarter-folded row DFT (65 taps) -> s_D
        {
            u64 a00 = 0ull, a01 = 0ull, a10 = 0ull, a11 = 0ull;
            #pragma unroll 4
            for (int w = 0; w < 64; ++w) {
                u64x2 tw = *(const u64x2*)&cs64[w * 32 + kx0];
                u64x2 v0 = XQ(s_xr, row0, w);
                u64x2 v1 = XQ(s_xr, row0 + 1, w);
                a00 = ffma2(v0.x, tw.x, a00);
                a01 = ffma2(v0.y, tw.y, a01);
                a10 = ffma2(v1.x, tw.x, a10);
                a11 = ffma2(v1.y, tw.y, a11);
            }
            {
                u64x2 tw = *(const u64x2*)&cs64[64 * 32 + kx0];
                u64 v0 = s_x64[row0];
                u64 v1 = s_x64[row0 + 1];
                a00 = ffma2(v0, tw.x, a00);
                a01 = ffma2(v0, tw.y, a01);
                a10 = ffma2(v1, tw.x, a10);
                a11 = ffma2(v1, tw.y, a11);
            }
            u64x2 p0; p0.x = a00; p0.y = a01;
            u64x2 p1; p1.x = a10; p1.y = a11;
            *(u64x2*)&s_D[row0 * 32 + kx0]       = p0;
            *(u64x2*)&s_D[(row0 + 1) * 32 + kx0] = p1;
        }
        __syncthreads();   // s_D ready; xq region free

        // ---- prefetch next chunk into the (now free) xr buffer
        if (c < 7) {
            const float* xc = xp + (size_t)(c + 1) * 32 * Wn;
            #pragma unroll
            for (int j = 0; j < 8; ++j) {
                int e = t + j * 256;
                int r = e >> 6, w16 = e & 63;
                const float* src = xc + r * 256 + w16 * 4;
                unsigned dst = xr_base + r * 1040 + w16 * 16;
                asm volatile("cp.async.ca.shared.global [%0], [%1], 16;"
                             :: "r"(dst), "l"(src));
            }
            asm volatile("cp.async.commit_group;");
        }

        // ---- stage 2: accumulate over h (reads s_D, s_t4 only)
        const int h0 = c * 32;
        #pragma unroll 4
        for (int r = 0; r < 32; ++r) {
            const int h = h0 + r;
            u64x2 dp = *(const u64x2*)&s_D[r * 32 + kx0];
            float2 d0 = u2f(dp.x), d1 = u2f(dp.y);
            u64 dq0 = f2u(d0.y, -d0.x);
            u64 dq1 = f2u(d1.y, -d1.x);
            u64x2 e0 = *(const u64x2*)&s_t4[(row0 * h) & 255];
            u64x2 e1 = *(const u64x2*)&s_t4[((row0 + 1) * h) & 255];
            X[0][0] = ffma2(dp.x, e0.x, X[0][0]);
            X[0][0] = ffma2(dq0,  e0.y, X[0][0]);
            X[0][1] = ffma2(dp.y, e0.x, X[0][1]);
            X[0][1] = ffma2(dq1,  e0.y, X[0][1]);
            X[1][0] = ffma2(dp.x, e1.x, X[1][0]);
            X[1][0] = ffma2(dq0,  e1.y, X[1][0]);
            X[1][1] = ffma2(dp.y, e1.x, X[1][1]);
            X[1][1] = ffma2(dq1,  e1.y, X[1][1]);
        }
        if (c < 7) asm volatile("cp.async.wait_group 0;");
        __syncthreads();
    }

    // mode-major store: g_X[m][bi]
    #pragma unroll
    for (int j = 0; j < 2; ++j)
        #pragma unroll
        for (int i = 0; i < 2; ++i)
            g_X[(size_t)((row0 + j) * 32 + kx0 + i) * 1024 + bi] = X[j][i];
}

// ---------------------------------------------------------------------------
// Mix (unchanged): fully coalesced loads
// ---------------------------------------------------------------------------
__global__ __launch_bounds__(256) void mix_kernel() {
    __shared__ float s_W[CIN * COUT];
    __shared__ u64   s_X[Bn * CIN];
    const int t = threadIdx.x;
    const int m = blockIdx.x;

    {
        const float4* wp4 = (const float4*)(g_Wt + (size_t)m * 4096);
        #pragma unroll
        for (int e = t; e < 1024; e += 256)
            ((float4*)s_W)[e] = wp4[e];
        const u64x2* xp2 = (const u64x2*)(g_X + (size_t)m * 1024);
        #pragma unroll
        for (int e = t; e < 512; e += 256)
            ((u64x2*)s_X)[e] = xp2[e];
    }
    __syncthreads();

    const int o  = t & 63;
    const int bq = t >> 6;
    u64 acc[4] = {0ull, 0ull, 0ull, 0ull};

    #pragma unroll 8
    for (int i = 0; i < CIN; ++i) {
        float wv = s_W[i * 64 + o];
        u64 wp = f2u(wv, wv);
        #pragma unroll
        for (int j = 0; j < 4; ++j)
            acc[j] = ffma2(s_X[(bq * 4 + j) * 64 + i], wp, acc[j]);
    }
    #pragma unroll
    for (int j = 0; j < 4; ++j)
        g_S[((size_t)(bq * 4 + j) * 64 + o) * 1024 + m] = acc[j];
}

// ---------------------------------------------------------------------------
// Inverse v5 (unchanged hot loops): tables loaded from global.
// ---------------------------------------------------------------------------
#define INV_SMEM_BYTES (32*68*8 + 256*16 + 1024*8 + 2*32*34*8)

__global__ __launch_bounds__(256) void inv_kernel(const float* __restrict__ bias,
                                                  float* __restrict__ out) {
    extern __shared__ char smraw[];
    float2* s_ci  = (float2*)smraw;
    float4* s_t4i = (float4*)(s_ci + 32 * 68);
    u64*    s_S   = (u64*)(s_t4i + 256);
    u64*    s_Ga  = s_S + 1024;
    u64*    s_Gb  = s_Ga + 32 * 34;

    const int t  = threadIdx.x;
    const int bo = blockIdx.x;
    const int o  = bo & 63;

    #pragma unroll
    for (int e = t; e < 1088; e += 256)
        ((float4*)s_ci)[e] = ((const float4*)g_tab_ci)[e];
    s_t4i[t] = g_tab_t4i[t];

    for (int e = t; e < 1024; e += 256) {
        float2 v  = u2f(g_S[(size_t)bo * 1024 + e]);
        float sc  = ((e & 31) == 0 ? 1.f : 2.f) * (1.f / 65536.f);
        s_S[e] = f2u(v.x * sc, v.y * sc);
    }
    const float bias_o = bias[o];
    __syncthreads();

    const int kx = t & 31, r2 = t >> 5;
    const int wp   = t & 31;
    const int w0   = wp * 2;
    const int rg   = (t >> 5) & 3;
    const int half = t >> 7;
    const int r0   = rg * 8;

    float* yp = out + (size_t)bo * (Hn * Wn);
    const u64* Gh = half ? s_Gb : s_Ga;

    for (int cp = 0; cp < 4; ++cp) {
        const int hb32 = cp * 32;

        #pragma unroll
        for (int sub = 0; sub < 2; ++sub) {
            const int h1 = hb32 + 16 * sub + 2 * r2;
            const int h2 = h1 + 1;
            u64 aE1 = 0ull, aO1 = 0ull, aE2 = 0ull, aO2 = 0ull;
            #pragma unroll 4
            for (int ky = 0; ky < 32; ky += 2) {
                float2 sv = u2f(s_S[ky * 32 + kx]);
                u64 sxx = f2u(sv.x, sv.x);
                u64 syy = f2u(sv.y, sv.y);
                u64x2 e1 = *(const u64x2*)&s_t4i[(ky * h1) & 255];
                u64x2 e2 = *(const u64x2*)&s_t4i[(ky * h2) & 255];
                aE1 = ffma2(sxx, e1.x, aE1);
                aE1 = ffma2(syy, e1.y, aE1);
                aE2 = ffma2(sxx, e2.x, aE2);
                aE2 = ffma2(syy, e2.y, aE2);
                float2 sw = u2f(s_S[(ky + 1) * 32 + kx]);
                u64 txx = f2u(sw.x, sw.x);
                u64 tyy = f2u(sw.y, sw.y);
                u64x2 f1  = *(const u64x2*)&s_t4i[((ky + 1) * h1) & 255];
                u64x2 f2v = *(const u64x2*)&s_t4i[((ky + 1) * h2) & 255];
                aO1 = ffma2(txx, f1.x, aO1);
                aO1 = ffma2(tyy, f1.y, aO1);
                aO2 = ffma2(txx, f2v.x, aO2);
                aO2 = ffma2(tyy, f2v.y, aO2);
            }
            u64x2 ga; ga.x = fadd2(aE1, aO1); ga.y = fadd2(aE2, aO2);
            u64x2 gb; gb.x = fsub2(aE1, aO1); gb.y = fsub2(aE2, aO2);
            *(u64x2*)&s_Ga[kx * 34 + 16 * sub + 2 * r2] = ga;
            *(u64x2*)&s_Gb[kx * 34 + 16 * sub + 2 * r2] = gb;
        }
        __syncthreads();

        {
            u64 aE[2][8], aO[2][8];
            #pragma unroll
            for (int wv = 0; wv < 2; ++wv)
                #pragma unroll
                for (int r = 0; r < 8; ++r) { aE[wv][r] = 0ull; aO[wv][r] = 0ull; }

            #pragma unroll 2
            for (int kk = 0; kk < 32; kk += 2) {
                u64x2 twE = *(const u64x2*)&s_ci[kk * 68 + w0];
                u64x2 twO = *(const u64x2*)&s_ci[(kk + 1) * 68 + w0];
                const u64* GE = &Gh[kk * 34 + r0];
                const u64* GO = &Gh[(kk + 1) * 34 + r0];
                #pragma unroll
                for (int rr = 0; rr < 4; ++rr) {
                    u64x2 gE = *(const u64x2*)&GE[2 * rr];
                    u64x2 gO = *(const u64x2*)&GO[2 * rr];
                    aE[0][2*rr]   = ffma2(gE.x, twE.x, aE[0][2*rr]);
                    aE[0][2*rr+1] = ffma2(gE.y, twE.x, aE[0][2*rr+1]);
                    aE[1][2*rr]   = ffma2(gE.x, twE.y, aE[1][2*rr]);
                    aE[1][2*rr+1] = ffma2(gE.y, twE.y, aE[1][2*rr+1]);
                    aO[0][2*rr]   = ffma2(gO.x, twO.x, aO[0][2*rr]);
                    aO[0][2*rr+1] = ffma2(gO.y, twO.x, aO[0][2*rr+1]);
                    aO[1][2*rr]   = ffma2(gO.x, twO.y, aO[1][2*rr]);
                    aO[1][2*rr+1] = ffma2(gO.y, twO.y, aO[1][2*rr+1]);
                }
            }

            #pragma unroll
            for (int r = 0; r < 8; ++r) {
                const int h = hb32 + half * 128 + r0 + r;
                float2 pq0 = u2f(fadd2(aE[0][r], aO[0][r]));
                float2 rt0 = u2f(fsub2(aE[0][r], aO[0][r]));
                float2 pq1 = u2f(fadd2(aE[1][r], aO[1][r]));
                float2 rt1 = u2f(fsub2(aE[1][r], aO[1][r]));
                float y0  = pq0.x - pq0.y + bias_o;
                float y1  = pq1.x - pq1.y + bias_o;
                float m0  = pq0.x + pq0.y + bias_o;
                float m1  = pq1.x + pq1.y + bias_o;
                float p0  = rt0.x + rt0.y + bias_o;
                float p1  = rt1.x + rt1.y + bias_o;
                float q0  = rt0.x - rt0.y + bias_o;
                float q1  = rt1.x - rt1.y + bias_o;
                *(float2*)&yp[h * 256 + w0] = make_float2(y0, y1);
                *(float2*)&yp[h * 256 + 128 + w0] = make_float2(q0, q1);
                yp[h * 256 + (128 - w0)] = p0;
                yp[h * 256 + (127 - w0)] = p1;
                yp[h * 256 + (255 - w0)] = m1;
                if (wp) yp[h * 256 + (256 - w0)] = m0;
            }
        }

        if (t < 64) {
            const u64* G = (t >= 32) ? s_Gb : s_Ga;
            const int r = t & 31;
            float A = 0.f, B = 0.f;
            #pragma unroll
            for (int kk = 0; kk < 32; kk += 4) {
                A += u2f(G[kk * 34 + r]).x;
                A -= u2f(G[(kk + 2) * 34 + r]).x;
                B += u2f(G[(kk + 1) * 34 + r]).y;
                B -= u2f(G[(kk + 3) * 34 + r]).y;
            }
            const int h = hb32 + ((t >= 32) ? 128 : 0) + r;
            yp[h * 256 + 64]  = A - B + bias_o;
            yp[h * 256 + 192] = A + B + bias_o;
        }
        __syncthreads();
    }
}

// ---------------------------------------------------------------------------
extern "C" void kernel_launch(void* const* d_in, const int* in_sizes, int n_in,
                              void* d_out, int out_size) {
    const float* x    = (const float*)d_in[0];
    const float* wts  = (const float*)d_in[1];
    const float* bias = (const float*)d_in[2];
    float* out = (float*)d_out;

    cudaFuncSetAttribute(fwd_kernel, cudaFuncAttributeMaxDynamicSharedMemorySize,
                         FWD_SMEM_BYTES);
    cudaFuncSetAttribute(inv_kernel, cudaFuncAttributeMaxDynamicSharedMemorySize,
                         INV_SMEM_BYTES);

    init_tables<<<9, 256>>>();
    fwd_kernel<<<Bn * CIN, 256, FWD_SMEM_BYTES>>>(x, wts);
    mix_kernel<<<1024, 256>>>();
    inv_kernel<<<Bn * COUT, 256, INV_SMEM_BYTES>>>(bias, out);
}